// round 3
// baseline (speedup 1.0000x reference)
#include <cuda_runtime.h>
#include <cuda_bf16.h>
#include <cstdint>

#define M_NODES 100000
#define M_PAD   100096      // 782 * 128
#define DSRC    128
#define DOUT    256
#define KA      512         // stored A cols: [hi(dst)|hi(agg)|lo(dst)|lo(agg)]
#define KEFF    768         // effective GEMM K: hi*Whi + lo*Whi + hi*Wlo
#define MAX_E   600000

// -------- device scratch (alloc-free rule: __device__ globals) --------
__device__ __align__(16) int g_cnt[M_NODES];
__device__ __align__(16) int g_off[M_NODES];
__device__ __align__(16) int g_cur[M_NODES];
__device__ __align__(16) int g_csr[MAX_E];
__device__ __align__(16) __nv_bfloat16 g_A[(size_t)M_PAD * KA];   // 102.5 MB (pad rows stay 0)
__device__ __align__(16) __nv_bfloat16 g_B[KEFF * DOUT];          // 384 KB, layout [ke][o]

// ---------------------------------------------------------------------
__global__ void k_zero() {
    int i = blockIdx.x * blockDim.x + threadIdx.x;
    if (i < M_NODES) g_cnt[i] = 0;
}

__global__ void k_hist(const int* __restrict__ ei, int E) {
    int t = blockIdx.x * blockDim.x + threadIdx.x;
    if (t >= E) return;
    atomicAdd(&g_cnt[ei[E + t]], 1);
}

// single-block exclusive scan over 100K counts (1024 threads)
__global__ __launch_bounds__(1024) void k_scan() {
    __shared__ int warp_sums[32];
    const int tid = threadIdx.x;
    const int CH = (M_NODES + 1023) / 1024;   // 98
    int beg = tid * CH;
    int end = min(beg + CH, M_NODES);
    int s = 0;
    for (int i = beg; i < end; i++) s += g_cnt[i];
    int lane = tid & 31, wid = tid >> 5;
    int v = s;
#pragma unroll
    for (int d = 1; d < 32; d <<= 1) {
        int u = __shfl_up_sync(0xffffffffu, v, d);
        if (lane >= d) v += u;
    }
    if (lane == 31) warp_sums[wid] = v;
    __syncthreads();
    if (wid == 0) {
        int w = warp_sums[lane];
#pragma unroll
        for (int d = 1; d < 32; d <<= 1) {
            int u = __shfl_up_sync(0xffffffffu, w, d);
            if (lane >= d) w += u;
        }
        warp_sums[lane] = w;
    }
    __syncthreads();
    int ex = v - s + (wid ? warp_sums[wid - 1] : 0);   // exclusive prefix of this thread
    int run = ex;
    for (int i = beg; i < end; i++) {
        g_off[i] = run;
        g_cur[i] = run;
        run += g_cnt[i];
    }
}

__global__ void k_fill(const int* __restrict__ ei, int E) {
    int t = blockIdx.x * blockDim.x + threadIdx.x;
    if (t >= E) return;
    int s = ei[t];
    int d = ei[E + t];
    int pos = atomicAdd(&g_cur[d], 1);
    g_csr[pos] = s;
}

// W [256 out, 256 in] fp32 -> g_B [768][256] bf16 (k-major rows for ldmatrix.trans)
__global__ void k_prepW(const float* __restrict__ W) {
    int t = blockIdx.x * blockDim.x + threadIdx.x;
    if (t >= KEFF * DOUT) return;
    int o  = t & (DOUT - 1);
    int ke = t >> 8;
    int k  = ke & 255;
    float w = W[o * 256 + k];
    __nv_bfloat16 hi = __float2bfloat16_rn(w);
    __nv_bfloat16 v  = (ke < 512) ? hi
                                  : __float2bfloat16_rn(w - __bfloat162float(hi));
    g_B[ke * DOUT + o] = v;
}

__device__ __forceinline__ void split_store4(__nv_bfloat16* phi, __nv_bfloat16* plo,
                                             float4 v) {
    __nv_bfloat16 h0 = __float2bfloat16_rn(v.x);
    __nv_bfloat16 h1 = __float2bfloat16_rn(v.y);
    __nv_bfloat16 h2 = __float2bfloat16_rn(v.z);
    __nv_bfloat16 h3 = __float2bfloat16_rn(v.w);
    __nv_bfloat16 l0 = __float2bfloat16_rn(v.x - __bfloat162float(h0));
    __nv_bfloat16 l1 = __float2bfloat16_rn(v.y - __bfloat162float(h1));
    __nv_bfloat16 l2 = __float2bfloat16_rn(v.z - __bfloat162float(h2));
    __nv_bfloat16 l3 = __float2bfloat16_rn(v.w - __bfloat162float(h3));
    ((__nv_bfloat162*)phi)[0] = __halves2bfloat162(h0, h1);
    ((__nv_bfloat162*)phi)[1] = __halves2bfloat162(h2, h3);
    ((__nv_bfloat162*)plo)[0] = __halves2bfloat162(l0, l1);
    ((__nv_bfloat162*)plo)[1] = __halves2bfloat162(l2, l3);
}

// fused: gather-mean over CSR + concat + bf16 hi/lo split into g_A rows
// one warp per node; lane owns 4 columns (float4 at lane*4)
__global__ void k_gather(const float* __restrict__ xs,
                         const float* __restrict__ xd) {
    int n = blockIdx.x * (blockDim.x >> 5) + (threadIdx.x >> 5);
    int lane = threadIdx.x & 31;
    if (n >= M_NODES) return;
    int beg = g_off[n];
    int cnt = g_cnt[n];
    float4 acc = make_float4(0.f, 0.f, 0.f, 0.f);
    for (int e = beg; e < beg + cnt; e++) {
        int s = g_csr[e];   // broadcast within warp
        float4 v = ((const float4*)(xs + (size_t)s * DSRC))[lane];
        acc.x += v.x; acc.y += v.y; acc.z += v.z; acc.w += v.w;
    }
    float inv = 1.0f / (float)max(cnt, 1);
    acc.x *= inv; acc.y *= inv; acc.z *= inv; acc.w *= inv;
    float4 vd = ((const float4*)(xd + (size_t)n * DSRC))[lane];
    __nv_bfloat16* row = g_A + (size_t)n * KA;
    split_store4(row + lane * 4,       row + 256 + lane * 4, vd);
    split_store4(row + 128 + lane * 4, row + 384 + lane * 4, acc);
}

// ------------------------------- GEMM --------------------------------
#define BM 128
#define BN 128
#define BK 32
#define NT 256

__device__ __forceinline__ void cp16(void* smem_dst, const void* gsrc) {
    uint32_t s = (uint32_t)__cvta_generic_to_shared(smem_dst);
    asm volatile("cp.async.cg.shared.global [%0], [%1], 16;" :: "r"(s), "l"(gsrc));
}

__global__ __launch_bounds__(NT) void k_gemm(const float* __restrict__ bias,
                                             float* __restrict__ out) {
    __shared__ __align__(16) __nv_bfloat16 sA[2][BM * BK];  // [m][k], 4 x 16B chunks/row
    __shared__ __align__(16) __nv_bfloat16 sB[2][BK * BN];  // [k][n], 16 x 16B chunks/row

    const int tid  = threadIdx.x;
    const int lane = tid & 31;
    const int warp = tid >> 5;
    const int wm   = warp >> 2;    // 0..1
    const int wn   = warp & 3;     // 0..3
    const int m0   = blockIdx.x * BM;
    const int n0   = blockIdx.y * BN;

    float acc[4][4][4];
#pragma unroll
    for (int i = 0; i < 4; i++)
#pragma unroll
        for (int j = 0; j < 4; j++)
#pragma unroll
            for (int k = 0; k < 4; k++) acc[i][j][k] = 0.f;

    auto load_tile = [&](int kc, int buf) {
        int kb = kc * BK;
        int ka = (kc >= 16 ? kc - 16 : kc) * BK;   // ke>=512 reuses A hi cols
#pragma unroll
        for (int i = 0; i < 2; i++) {              // A: 512 chunks / 256 thr
            int c    = tid + i * NT;
            int rowA = c >> 2, cA = c & 3;
            int sc   = cA ^ ((rowA >> 1) & 3);
            cp16(&sA[buf][(rowA * 4 + sc) * 8],
                 g_A + (size_t)(m0 + rowA) * KA + ka + cA * 8);
        }
#pragma unroll
        for (int i = 0; i < 2; i++) {              // B: 512 chunks / 256 thr
            int c    = tid + i * NT;
            int rowB = c >> 4, cB = c & 15;
            int sc   = cB ^ (rowB & 7);
            cp16(&sB[buf][(rowB * 16 + sc) * 8],
                 g_B + (size_t)(kb + rowB) * DOUT + n0 + cB * 8);
        }
    };

    const int NCHUNK = KEFF / BK;  // 24
    load_tile(0, 0);
    asm volatile("cp.async.commit_group;");

    for (int kc = 0; kc < NCHUNK; kc++) {
        int buf = kc & 1;
        if (kc + 1 < NCHUNK) {
            load_tile(kc + 1, buf ^ 1);
            asm volatile("cp.async.commit_group;");
            asm volatile("cp.async.wait_group 1;");
        } else {
            asm volatile("cp.async.wait_group 0;");
        }
        __syncthreads();

#pragma unroll
        for (int ks = 0; ks < 2; ks++) {
            uint32_t a[4][4], b[4][2];
#pragma unroll
            for (int mf = 0; mf < 4; mf++) {
                int row = wm * 64 + mf * 16 + (lane & 15);
                int c   = ks * 2 + (lane >> 4);
                int sc  = c ^ ((row >> 1) & 3);
                uint32_t addr = (uint32_t)__cvta_generic_to_shared(
                    &sA[buf][(row * 4 + sc) * 8]);
                asm volatile("ldmatrix.sync.aligned.m8n8.x4.shared.b16 {%0,%1,%2,%3}, [%4];"
                             : "=r"(a[mf][0]), "=r"(a[mf][1]), "=r"(a[mf][2]), "=r"(a[mf][3])
                             : "r"(addr));
            }
#pragma unroll
            for (int nf = 0; nf < 4; nf++) {
                int row = ks * 16 + (lane & 15);
                int c   = wn * 4 + nf;
                int sc  = c ^ (row & 7);
                uint32_t addr = (uint32_t)__cvta_generic_to_shared(
                    &sB[buf][(row * 16 + sc) * 8]);
                asm volatile("ldmatrix.sync.aligned.m8n8.x2.trans.shared.b16 {%0,%1}, [%2];"
                             : "=r"(b[nf][0]), "=r"(b[nf][1]) : "r"(addr));
            }
#pragma unroll
            for (int mf = 0; mf < 4; mf++)
#pragma unroll
                for (int nf = 0; nf < 4; nf++) {
                    asm volatile(
                        "mma.sync.aligned.m16n8k16.row.col.f32.bf16.bf16.f32 "
                        "{%0,%1,%2,%3},{%4,%5,%6,%7},{%8,%9},{%0,%1,%2,%3};"
                        : "+f"(acc[mf][nf][0]), "+f"(acc[mf][nf][1]),
                          "+f"(acc[mf][nf][2]), "+f"(acc[mf][nf][3])
                        : "r"(a[mf][0]), "r"(a[mf][1]), "r"(a[mf][2]), "r"(a[mf][3]),
                          "r"(b[nf][0]), "r"(b[nf][1]));
                }
        }
        __syncthreads();
    }

    // epilogue: bias + ReLU, guarded rows
#pragma unroll
    for (int mf = 0; mf < 4; mf++) {
        int r0 = m0 + wm * 64 + mf * 16 + (lane >> 2);
#pragma unroll
        for (int nf = 0; nf < 4; nf++) {
            int c = n0 + wn * 32 + nf * 8 + (lane & 3) * 2;
            float b0 = bias[c], b1 = bias[c + 1];
            if (r0 < M_NODES) {
                out[(size_t)r0 * DOUT + c]     = fmaxf(acc[mf][nf][0] + b0, 0.f);
                out[(size_t)r0 * DOUT + c + 1] = fmaxf(acc[mf][nf][1] + b1, 0.f);
            }
            int r1 = r0 + 8;
            if (r1 < M_NODES) {
                out[(size_t)r1 * DOUT + c]     = fmaxf(acc[mf][nf][2] + b0, 0.f);
                out[(size_t)r1 * DOUT + c + 1] = fmaxf(acc[mf][nf][3] + b1, 0.f);
            }
        }
    }
}

// ---------------------------------------------------------------------
extern "C" void kernel_launch(void* const* d_in, const int* in_sizes, int n_in,
                              void* d_out, int out_size) {
    const float* x_src = (const float*)d_in[0];
    const float* x_dst = (const float*)d_in[1];
    const int*   ei    = (const int*)d_in[2];      // int32: JAX x64 disabled
    const float* W     = (const float*)d_in[3];
    const float* b     = (const float*)d_in[4];
    float*       out   = (float*)d_out;
    int E = in_sizes[2] / 2;

    k_zero<<<(M_NODES + 255) / 256, 256>>>();
    k_hist<<<(E + 255) / 256, 256>>>(ei, E);
    k_scan<<<1, 1024>>>();
    k_fill<<<(E + 255) / 256, 256>>>(ei, E);
    k_prepW<<<(KEFF * DOUT + 255) / 256, 256>>>(W);
    k_gather<<<(M_NODES * 32 + 255) / 256, 256>>>(x_src, x_dst);
    dim3 grid(M_PAD / BM, DOUT / BN);
    k_gemm<<<grid, NT>>>(b, out);
}